// round 16
// baseline (speedup 1.0000x reference)
#include <cuda_runtime.h>

#define NN    100000
#define EE    1600000
#define HID   64
#define HID2  128
#define EDIM  16
#define INDIM 32

// ---------------- scratch (device globals; no allocation) ----------------
__device__ float  g_hA[NN * HID];
__device__ float  g_hB[NN * HID];
__device__ float  g_tmp[NN * HID];
__device__ int    g_deg[NN];
__device__ int    g_cnt[NN];
__device__ int    g_rowptr[NN + 1];
__device__ int    g_blksum[256];
__device__ int    g_srcp[EE];          // src index permuted to CSR order
__device__ float4 g_eap[EE * 4];       // edge_attr permuted to CSR order (64 B/edge)

// ---------------- cp.async + f32x2 helpers ----------------
__device__ __forceinline__ void cp_async16(void* dst, const void* src) {
    unsigned int d = (unsigned int)__cvta_generic_to_shared(dst);
    asm volatile("cp.async.ca.shared.global [%0], [%1], 16;" :: "r"(d), "l"(src) : "memory");
}
__device__ __forceinline__ void cp_async8(void* dst, const void* src) {
    unsigned int d = (unsigned int)__cvta_generic_to_shared(dst);
    asm volatile("cp.async.ca.shared.global [%0], [%1], 8;" :: "r"(d), "l"(src) : "memory");
}
__device__ __forceinline__ void cp_commit() {
    asm volatile("cp.async.commit_group;" ::: "memory");
}
__device__ __forceinline__ void cp_wait1() {
    asm volatile("cp.async.wait_group 1;" ::: "memory");
}

__device__ __forceinline__ unsigned long long fma2(unsigned long long a,
                                                   unsigned long long b,
                                                   unsigned long long c) {
    unsigned long long d;
    asm("fma.rn.f32x2 %0, %1, %2, %3;" : "=l"(d) : "l"(a), "l"(b), "l"(c));
    return d;
}
__device__ __forceinline__ unsigned long long pack2(float lo, float hi) {
    unsigned long long d;
    asm("mov.b64 %0, {%1, %2};" : "=l"(d)
        : "r"(__float_as_uint(lo)), "r"(__float_as_uint(hi)));
    return d;
}
__device__ __forceinline__ float hadd2(unsigned long long p) {
    unsigned int lo, hi;
    asm("mov.b64 {%0, %1}, %2;" : "=r"(lo), "=r"(hi) : "l"(p));
    return __uint_as_float(lo) + __uint_as_float(hi);
}

union F4U { float4 f4; unsigned long long u[2]; };

// ---------------- CSR build ----------------
__global__ void k_zero(int N) {
    int i = blockIdx.x * blockDim.x + threadIdx.x;
    if (i < N) { g_deg[i] = 0; g_cnt[i] = 0; }
}

__global__ void k_hist(const int* __restrict__ dst, int E) {
    int e = blockIdx.x * blockDim.x + threadIdx.x;
    if (e < E) atomicAdd(&g_deg[dst[e]], 1);
}

__global__ void k_scan1(int N) {
    __shared__ int sh[1024];
    int i = blockIdx.x * 1024 + threadIdx.x;
    int v = (i < N) ? g_deg[i] : 0;
    sh[threadIdx.x] = v;
    __syncthreads();
    for (int off = 1; off < 1024; off <<= 1) {
        int add = (threadIdx.x >= off) ? sh[threadIdx.x - off] : 0;
        __syncthreads();
        sh[threadIdx.x] += add;
        __syncthreads();
    }
    if (i < N) g_rowptr[i] = sh[threadIdx.x] - v;     // exclusive
    if (threadIdx.x == 1023) g_blksum[blockIdx.x] = sh[1023];
}

__global__ void k_scan2(int B) {
    if (blockIdx.x == 0 && threadIdx.x == 0) {
        int acc = 0;
        for (int b = 0; b < B; b++) { int t = g_blksum[b]; g_blksum[b] = acc; acc += t; }
    }
}

__global__ void k_scan3(int N, int E) {
    int i = blockIdx.x * 1024 + threadIdx.x;
    if (i < N) g_rowptr[i] += g_blksum[blockIdx.x];
    if (i == 0) g_rowptr[N] = E;
}

// scatter: build CSR-permuted src and edge_attr streams
__global__ void k_scatter(const int* __restrict__ src, const int* __restrict__ dst,
                          const float4* __restrict__ ea, int E) {
    int e = blockIdx.x * blockDim.x + threadIdx.x;
    if (e >= E) return;
    int d = dst[e];
    int p = g_rowptr[d] + atomicAdd(&g_cnt[d], 1);
    g_srcp[p] = src[e];
    float4 a0 = __ldg(ea + e * 4 + 0);
    float4 a1 = __ldg(ea + e * 4 + 1);
    float4 a2 = __ldg(ea + e * 4 + 2);
    float4 a3 = __ldg(ea + e * 4 + 3);
    g_eap[p * 4 + 0] = a0;
    g_eap[p * 4 + 1] = a1;
    g_eap[p * 4 + 2] = a2;
    g_eap[p * 4 + 3] = a3;
}

// ---------------- input linear: h = x @ src_w + src_b ----------------
__global__ void k_inlin(const float* __restrict__ x, const float* __restrict__ w,
                        const float* __restrict__ b, int N) {
    int idx = blockIdx.x * blockDim.x + threadIdx.x;
    if (idx >= N * HID) return;
    int n = idx >> 6, c = idx & 63;
    const float* xr = x + n * INDIM;
    float acc = __ldg(&b[c]);
#pragma unroll
    for (int k = 0; k < INDIM; k++)
        acc = fmaf(__ldg(&xr[k]), __ldg(&w[k * HID + c]), acc);
    g_hA[idx] = acc;
}

// ---------------- aggregation: warp-per-node, cp.async double-buffer --------
// (unchanged from R13 — it delivered the 846->664 win)
__global__ void __launch_bounds__(256)
k_agg(int dir, const float* __restrict__ ew, const float* __restrict__ ebias, int N) {
    const float* hin = dir ? g_hB : g_hA;
    __shared__ float4 s_attr[8][2][32];       // [warp][stage][8 edges * 4 float4] = 8 KB
    __shared__ float2 s_h[8][2][8][32];       // [warp][stage][edge][lane]        = 32 KB

    int warp = threadIdx.x >> 5, lane = threadIdx.x & 31;
    int n = blockIdx.x * 8 + warp;
    if (n >= N) return;

    float2 ewr[EDIM];
#pragma unroll
    for (int k = 0; k < EDIM; k++)
        ewr[k] = __ldg((const float2*)(ew + k * HID) + lane);
    float2 eb = __ldg((const float2*)ebias + lane);
    float2 hs = __ldg((const float2*)(hin + n * HID) + lane);   // self feature

    int beg = g_rowptr[n], end = g_rowptr[n + 1];
    int deg = end - beg;
    float s0 = 0.f, s1 = 0.f, t0 = 0.f, t1 = 0.f;

#define STAGE(SIDX, ESTART) do {                                               \
        int _m = end - (ESTART);                                               \
        if (_m > 8) _m = 8;                                                    \
        if (_m > 0) {                                                          \
            if (lane < _m * 4)                                                 \
                cp_async16(&s_attr[warp][SIDX][lane],                          \
                           (const float4*)g_eap + (size_t)(ESTART) * 4 + lane);\
            _Pragma("unroll")                                                  \
            for (int _e = 0; _e < 8; _e++) {                                   \
                if (_e < _m) {                                                 \
                    int _sv = __ldg(&g_srcp[(ESTART) + _e]);                   \
                    cp_async8(&s_h[warp][SIDX][_e][lane],                      \
                              (const float2*)(hin + _sv * HID) + lane);        \
                }                                                              \
            }                                                                  \
        }                                                                      \
        cp_commit();                                                           \
    } while (0)

    int nb = (deg + 7) >> 3;
    STAGE(0, beg);
    STAGE(1, beg + 8);

    for (int b = 0; b < nb; b++) {
        cp_wait1();
        __syncwarp();
        int estart = beg + b * 8;
        int m = end - estart; if (m > 8) m = 8;
        int sidx = b & 1;
        for (int e = 0; e < m; e++) {
            const float4* sa = &s_attr[warp][sidx][e * 4];
            float4 a0 = sa[0], a1 = sa[1], a2 = sa[2], a3 = sa[3];
            float2 h = s_h[warp][sidx][e][lane];
            float av[16] = {a0.x, a0.y, a0.z, a0.w, a1.x, a1.y, a1.z, a1.w,
                            a2.x, a2.y, a2.z, a2.w, a3.x, a3.y, a3.z, a3.w};
            float v0 = eb.x, v1 = eb.y;
#pragma unroll
            for (int k = 0; k < EDIM; k++) {
                v0 = fmaf(av[k], ewr[k].x, v0);
                v1 = fmaf(av[k], ewr[k].y, v1);
            }
            float r0 = fmaxf(h.x + v0, 0.f);
            float r1 = fmaxf(h.y + v1, 0.f);
            float w0 = __expf(r0);
            float w1 = __expf(r1);
            s0 += w0;
            s1 += w1;
            t0 = fmaf(r0, w0, t0);
            t1 = fmaf(r1, w1, t1);
        }
        __syncwarp();
        STAGE(sidx, beg + (b + 2) * 8);
    }
#undef STAGE

    float o0 = (s0 > 0.f ? __fdividef(t0, s0) + 1e-7f : 0.f) + hs.x;
    float o1 = (s1 > 0.f ? __fdividef(t1, s1) + 1e-7f : 0.f) + hs.y;
    *((float2*)(g_tmp + n * HID) + lane) = make_float2(o0, o1);
}

// ---------------- MLP: Linear(64->128) -> BN -> ReLU -> Linear(128->64) -> ReLU
// reads g_tmp; dir=0: write g_hB; dir=1: write g_hA.
// 32 nodes per block, 256 threads; k-pair f32x2 packed inner products.
__global__ void __launch_bounds__(256)
k_mlp(int dir,
      const float* __restrict__ w1, const float* __restrict__ b1,
      const float* __restrict__ gam, const float* __restrict__ bet,
      const float* __restrict__ w2, const float* __restrict__ b2, int N) {
    float* outp = dir ? g_hA : g_hB;
    __shared__ float s_in[32][HID];     // 8 KB
    __shared__ float s_hh[32][HID2];    // 16 KB
    int tid = threadIdx.x;
    int base = blockIdx.x * 32;

    // stage 32 node rows (zero-fill past N)
    {
        const float4* src4 = (const float4*)(g_tmp + base * HID);
        float4* dst4 = (float4*)&s_in[0][0];
        long limit4 = (long)(N - base) * (HID / 4);
#pragma unroll
        for (int t = 0; t < 2; t++) {
            int i = tid + t * 256;
            dst4[i] = (i < limit4) ? __ldg(src4 + i) : make_float4(0.f, 0.f, 0.f, 0.f);
        }
    }
    __syncthreads();

    // phase 1: hh = relu(BN(in @ w1 + b1)); thread: 8 nodes x 2 adjacent j
    // k-pair f32x2: 2-wide accumulators, horizontal add at the end
    {
        int jp  = tid & 63;
        int grp = tid >> 6;
        unsigned long long A0[8], A1[8];
#pragma unroll
        for (int u = 0; u < 8; u++) { A0[u] = 0ull; A1[u] = 0ull; }
#pragma unroll
        for (int k4 = 0; k4 < HID; k4 += 4) {
            float2 wk0 = __ldg((const float2*)(w1 + (k4 + 0) * HID2) + jp);
            float2 wk1 = __ldg((const float2*)(w1 + (k4 + 1) * HID2) + jp);
            float2 wk2 = __ldg((const float2*)(w1 + (k4 + 2) * HID2) + jp);
            float2 wk3 = __ldg((const float2*)(w1 + (k4 + 3) * HID2) + jp);
            unsigned long long P0a = pack2(wk0.x, wk1.x);   // ch j0, k pair 0
            unsigned long long P0b = pack2(wk2.x, wk3.x);   // ch j0, k pair 1
            unsigned long long P1a = pack2(wk0.y, wk1.y);   // ch j1, k pair 0
            unsigned long long P1b = pack2(wk2.y, wk3.y);   // ch j1, k pair 1
#pragma unroll
            for (int u = 0; u < 8; u++) {
                F4U xv; xv.f4 = *(const float4*)&s_in[grp * 8 + u][k4];
                A0[u] = fma2(xv.u[0], P0a, A0[u]);
                A0[u] = fma2(xv.u[1], P0b, A0[u]);
                A1[u] = fma2(xv.u[0], P1a, A1[u]);
                A1[u] = fma2(xv.u[1], P1b, A1[u]);
            }
        }
        const float BNC = 0.9999950000375f;    // 1/sqrt(1+1e-5)
        float2 bb = __ldg((const float2*)b1 + jp);
        float2 gm = __ldg((const float2*)gam + jp);
        float2 bt = __ldg((const float2*)bet + jp);
        float g0 = gm.x * BNC, g1 = gm.y * BNC;
#pragma unroll
        for (int u = 0; u < 8; u++) {
            float acc0 = hadd2(A0[u]) + bb.x;
            float acc1 = hadd2(A1[u]) + bb.y;
            float2 hv;
            hv.x = fmaxf(fmaf(acc0, g0, bt.x), 0.f);
            hv.y = fmaxf(fmaf(acc1, g1, bt.y), 0.f);
            *((float2*)&s_hh[grp * 8 + u][0] + jp) = hv;
        }
    }
    __syncthreads();

    // phase 2: y = relu(hh @ w2 + b2); thread: 4 nodes x 2 adjacent c
    {
        int cp  = tid & 31;
        int grp = tid >> 5;
        unsigned long long A0[4], A1[4];
#pragma unroll
        for (int u = 0; u < 4; u++) { A0[u] = 0ull; A1[u] = 0ull; }
#pragma unroll
        for (int k4 = 0; k4 < HID2; k4 += 4) {
            float2 wk0 = __ldg((const float2*)(w2 + (k4 + 0) * HID) + cp);
            float2 wk1 = __ldg((const float2*)(w2 + (k4 + 1) * HID) + cp);
            float2 wk2 = __ldg((const float2*)(w2 + (k4 + 2) * HID) + cp);
            float2 wk3 = __ldg((const float2*)(w2 + (k4 + 3) * HID) + cp);
            unsigned long long P0a = pack2(wk0.x, wk1.x);
            unsigned long long P0b = pack2(wk2.x, wk3.x);
            unsigned long long P1a = pack2(wk0.y, wk1.y);
            unsigned long long P1b = pack2(wk2.y, wk3.y);
#pragma unroll
            for (int u = 0; u < 4; u++) {
                F4U xv; xv.f4 = *(const float4*)&s_hh[grp * 4 + u][k4];
                A0[u] = fma2(xv.u[0], P0a, A0[u]);
                A0[u] = fma2(xv.u[1], P0b, A0[u]);
                A1[u] = fma2(xv.u[0], P1a, A1[u]);
                A1[u] = fma2(xv.u[1], P1b, A1[u]);
            }
        }
        float2 bb = __ldg((const float2*)b2 + cp);
#pragma unroll
        for (int u = 0; u < 4; u++) {
            int node = base + grp * 4 + u;
            if (node < N) {
                float2 ov;
                ov.x = fmaxf(hadd2(A0[u]) + bb.x, 0.f);   // outer relu
                ov.y = fmaxf(hadd2(A1[u]) + bb.y, 0.f);
                *((float2*)(outp + node * HID) + cp) = ov;
            }
        }
    }
}

// ---------------- head ----------------
__global__ void k_head(const float* __restrict__ gfeat, const int* __restrict__ ngp,
                       const float* __restrict__ hw, const float* __restrict__ hb,
                       float* __restrict__ out, int N, int gfd) {
    int n = blockIdx.x * blockDim.x + threadIdx.x;
    if (n >= N) return;
    const float* h = g_hA;   // final features land in A (A->B->A)
    float acc = __ldg(&hb[0]);
#pragma unroll 8
    for (int c = 0; c < HID; c++)
        acc = fmaf(h[n * HID + c], __ldg(&hw[c]), acc);
    int G = *ngp;
    int npg = N / G;
    int g = n / npg, r = n - g * npg;
    for (int d = 0; d < gfd; d++)
        acc = fmaf(__ldg(&gfeat[(g * gfd + d) * npg + r]), __ldg(&hw[HID + d]), acc);
    out[n] = acc;
}

// ---------------- launch ----------------
extern "C" void kernel_launch(void* const* d_in, const int* in_sizes, int n_in,
                              void* d_out, int out_size) {
    const float* x     = (const float*)d_in[0];
    const int*   eidx  = (const int*)d_in[1];
    const float* eattr = (const float*)d_in[2];
    const int*   ngp   = (const int*)d_in[3];
    const float* gfeat = (const float*)d_in[4];
    const float* src_w = (const float*)d_in[5];
    const float* src_b = (const float*)d_in[6];

    int N   = in_sizes[0] / INDIM;
    int E   = in_sizes[1] / 2;
    int gfd = in_sizes[4] / N;

    const int* src = eidx;
    const int* dst = eidx + E;

    // CSR build + permuted edge streams
    k_zero<<<(N + 255) / 256, 256>>>(N);
    k_hist<<<(E + 255) / 256, 256>>>(dst, E);
    int nb = (N + 1023) / 1024;
    k_scan1<<<nb, 1024>>>(N);
    k_scan2<<<1, 32>>>(nb);
    k_scan3<<<nb, 1024>>>(N, E);
    k_scatter<<<(E + 255) / 256, 256>>>(src, dst, (const float4*)eattr, E);

    // h0 = x @ src_w + src_b   (writes g_hA)
    k_inlin<<<(N * HID + 255) / 256, 256>>>(x, src_w, src_b, N);

    // layer 0: hA -> tmp -> hB
    k_agg<<<(N + 7) / 8, 256>>>(0, (const float*)d_in[7], (const float*)d_in[8], N);
    k_mlp<<<(N + 31) / 32, 256>>>(0,
        (const float*)d_in[9],  (const float*)d_in[10],
        (const float*)d_in[11], (const float*)d_in[12],
        (const float*)d_in[13], (const float*)d_in[14], N);

    // layer 1: hB -> tmp -> hA
    k_agg<<<(N + 7) / 8, 256>>>(1, (const float*)d_in[15], (const float*)d_in[16], N);
    k_mlp<<<(N + 31) / 32, 256>>>(1,
        (const float*)d_in[17], (const float*)d_in[18],
        (const float*)d_in[19], (const float*)d_in[20],
        (const float*)d_in[21], (const float*)d_in[22], N);

    // head
    k_head<<<(N + 255) / 256, 256>>>(gfeat, ngp,
        (const float*)d_in[23], (const float*)d_in[24],
        (float*)d_out, N, gfd);
    (void)n_in; (void)out_size;
}